// round 11
// baseline (speedup 1.0000x reference)
#include <cuda_runtime.h>
#include <cstdint>

// GraphProjection, monolithic. History:
//  R4 coalesced scalar 90.1us -> R9 zero shortcut (h==0||w==0) 71.3
//  -> R10 aligned zero-fill 69.7. L1 port still binder (77%), slow path
//  dominates (120 load wf + ~60 store wf).
// R11: clip-collapse. P(h==223)~0.365 (Cauchy upper tail). When ceil(x)
// clamps (or x integral), xi1==xi2 -> Q11==Q21, Q12==Q22: fold weights and
// load HALF the rows. Both axes collapsed (13.3% of points): ONE row.
// Exactness: (w11+w21)*Q vs w11*Q+w21*Q differs ~1ulp; threshold 1e-3.

static constexpr int OUT_COLS = 963;

template <int C, int S>
__device__ __forceinline__ void bilerp_scalar(const float* __restrict__ feat,
                                              float x, float y,
                                              float* __restrict__ o, int lane) {
    float x1f = floorf(x), x2f = ceilf(x);
    float y1f = floorf(y), y2f = ceilf(y);
    int xi1 = (int)x1f, xi2 = (int)x2f, yi1 = (int)y1f, yi2 = (int)y2f;
    // JAX gather clamps; lower clamp also guards NaN->int conversion.
    if (xi1 < 0) xi1 = 0;
    if (yi1 < 0) yi1 = 0;
    if (xi2 < 0) xi2 = 0;
    if (yi2 < 0) yi2 = 0;
    if (xi1 > S - 1) xi1 = S - 1;
    if (yi1 > S - 1) yi1 = S - 1;
    if (xi2 > S - 1) xi2 = S - 1;
    if (yi2 > S - 1) yi2 = S - 1;

    float wa = (x2f - x) * (y2f - y);   // w11
    float wb = (x - x1f) * (y2f - y);   // w21
    float wc = (x2f - x) * (y - y1f);   // w12
    float wd = (x - x1f) * (y - y1f);   // w22

    // Row/column collapse after clamping: identical gather rows -> fold
    // weights and skip the duplicate loads. Warp-uniform predicates.
    bool xc = (xi1 == xi2);
    bool yc = (yi1 == yi2);
    if (xc) { wa += wb; wc += wd; }     // B folds into A, D into C
    if (yc) { wa += wc; wb += wd; }     // C folds into A, D into B

    const float* A = feat + (xi1 * S + yi1) * C;
    const float* B = feat + (xi2 * S + yi1) * C;
    const float* Cc = feat + (xi1 * S + yi2) * C;
    const float* D = feat + (xi2 * S + yi2) * C;

#pragma unroll
    for (int i = 0; i < C / 32; ++i) {
        int c = lane + 32 * i;
        float acc = wa * __ldg(A + c);
        if (!xc) acc += wb * __ldg(B + c);
        if (!yc) acc += wc * __ldg(Cc + c);
        if (!xc && !yc) acc += wd * __ldg(D + c);
        o[c] = acc;
    }
}

__global__ void __launch_bounds__(256)
graph_projection_kernel(const float* __restrict__ coord,
                        const float* __restrict__ f1,
                        const float* __restrict__ f2,
                        const float* __restrict__ f3,
                        const float* __restrict__ f4,
                        float* __restrict__ out, int N) {
    int p = (blockIdx.x * blockDim.x + threadIdx.x) >> 5;  // warp = point
    int lane = threadIdx.x & 31;
    if (p >= N) return;

    float X = __ldg(coord + 3 * p + 0);
    float Y = __ldg(coord + 3 * p + 1);
    float Z = __ldg(coord + 3 * p + 2);

    float h = 250.0f * (-Y) / (-Z) + 112.0f;
    float w = 250.0f * X / (-Z) + 112.0f;
    // clip to [0,223]; comparison form preserves jnp.clip NaN propagation
    h = (h < 0.0f) ? 0.0f : ((h > 223.0f) ? 223.0f : h);
    w = (w < 0.0f) ? 0.0f : ((w > 223.0f) ? 223.0f : w);

    float* __restrict__ orow = out + (size_t)p * OUT_COLS;
    if (lane == 0) orow[0] = X;
    if (lane == 1) orow[1] = Y;
    if (lane == 2) orow[2] = Z;

    // Fast path: h==0 or w==0 => x (or y) integral at every level =>
    // all four bilinear weights exactly 0 => 960-channel block is 0.
    if (h == 0.0f || w == 0.0f) {
        float* z = orow + 3;
        int head = (int)(((16u - ((uint32_t)(uintptr_t)z & 15u)) & 15u) >> 2);
        if (lane < head) z[lane] = 0.0f;
        int nvec = (960 - head) >> 2;
        float4* v = (float4*)(z + head);
        float4 z4 = make_float4(0.f, 0.f, 0.f, 0.f);
#pragma unroll
        for (int i = 0; i < 8; ++i) {
            int idx = lane + 32 * i;
            if (idx < nvec) v[idx] = z4;
        }
        int done = head + 4 * nvec;
        if (lane < 960 - done) z[done + lane] = 0.0f;
        return;
    }

    // scales: 224/56=4, 224/28=8, 224/14=16, 224/7=32 (exact pow2 -> mul ok)
    bilerp_scalar<64, 56>(f1, h * 0.25f,    w * 0.25f,    orow + 3,   lane);
    bilerp_scalar<128, 28>(f2, h * 0.125f,  w * 0.125f,   orow + 67,  lane);
    bilerp_scalar<256, 14>(f3, h * 0.0625f, w * 0.0625f,  orow + 195, lane);
    bilerp_scalar<512, 7>(f4, h * 0.03125f, w * 0.03125f, orow + 451, lane);
}

extern "C" void kernel_launch(void* const* d_in, const int* in_sizes, int n_in,
                              void* d_out, int out_size) {
    const float* coord = (const float*)d_in[0];
    const float* f1 = (const float*)d_in[1];
    const float* f2 = (const float*)d_in[2];
    const float* f3 = (const float*)d_in[3];
    const float* f4 = (const float*)d_in[4];
    float* out = (float*)d_out;

    int N = in_sizes[0] / 3;

    int blocks = (N + 7) / 8;  // 8 warps/block, 1 point/warp
    graph_projection_kernel<<<blocks, 256>>>(coord, f1, f2, f3, f4, out, N);
}

// round 12
// speedup vs baseline: 1.1325x; 1.1325x over previous
#include <cuda_runtime.h>
#include <cstdint>

// GraphProjection, monolithic. History:
//  R4 coalesced scalar 90.1 -> R9 zero shortcut 71.3 -> R10 aligned
//  zero-fill 69.7us. R11 clip-collapse with per-iteration predicated loads
//  REGRESSED to 76.6 (MLP destroyed: loads no longer front-batched).
// R12: same collapse algebra (xi1==xi2 after clamp => fold weights, skip
// duplicate rows; both axes => single row), but hoisted into 4 warp-uniform
// branch-free loop variants so every variant keeps unconditional fully
// unrolled load batches (max MLP), while collapsed variants issue 1/2 or
// 1/4 of the load wavefronts.

static constexpr int OUT_COLS = 963;

template <int C, int S>
__device__ __forceinline__ void bilerp_scalar(const float* __restrict__ feat,
                                              float x, float y,
                                              float* __restrict__ o, int lane) {
    float x1f = floorf(x), x2f = ceilf(x);
    float y1f = floorf(y), y2f = ceilf(y);
    int xi1 = (int)x1f, xi2 = (int)x2f, yi1 = (int)y1f, yi2 = (int)y2f;
    // JAX gather clamps; lower clamp also guards NaN->int conversion.
    if (xi1 < 0) xi1 = 0;
    if (yi1 < 0) yi1 = 0;
    if (xi2 < 0) xi2 = 0;
    if (yi2 < 0) yi2 = 0;
    if (xi1 > S - 1) xi1 = S - 1;
    if (yi1 > S - 1) yi1 = S - 1;
    if (xi2 > S - 1) xi2 = S - 1;
    if (yi2 > S - 1) yi2 = S - 1;

    float wa = (x2f - x) * (y2f - y);   // w11
    float wb = (x - x1f) * (y2f - y);   // w21
    float wc = (x2f - x) * (y - y1f);   // w12
    float wd = (x - x1f) * (y - y1f);   // w22

    const float* A = feat + (xi1 * S + yi1) * C;
    const float* B = feat + (xi2 * S + yi1) * C;
    const float* Cc = feat + (xi1 * S + yi2) * C;
    const float* D = feat + (xi2 * S + yi2) * C;

    bool xc = (xi1 == xi2);   // rows collapse (B==A, D==C)
    bool yc = (yi1 == yi2);   // cols collapse (C==A, D==B)

    if (xc && yc) {
        float wf = (wa + wb) + (wc + wd);
#pragma unroll
        for (int i = 0; i < C / 32; ++i) {
            int c = lane + 32 * i;
            o[c] = wf * __ldg(A + c);
        }
    } else if (xc) {
        float w0 = wa + wb, w1 = wc + wd;
#pragma unroll
        for (int i = 0; i < C / 32; ++i) {
            int c = lane + 32 * i;
            float a = __ldg(A + c);
            float cv = __ldg(Cc + c);
            o[c] = w0 * a + w1 * cv;
        }
    } else if (yc) {
        float w0 = wa + wc, w1 = wb + wd;
#pragma unroll
        for (int i = 0; i < C / 32; ++i) {
            int c = lane + 32 * i;
            float a = __ldg(A + c);
            float b = __ldg(B + c);
            o[c] = w0 * a + w1 * b;
        }
    } else {
#pragma unroll
        for (int i = 0; i < C / 32; ++i) {
            int c = lane + 32 * i;
            float a = __ldg(A + c);
            float b = __ldg(B + c);
            float cv = __ldg(Cc + c);
            float d = __ldg(D + c);
            o[c] = wa * a + wb * b + wc * cv + wd * d;
        }
    }
}

__global__ void __launch_bounds__(256)
graph_projection_kernel(const float* __restrict__ coord,
                        const float* __restrict__ f1,
                        const float* __restrict__ f2,
                        const float* __restrict__ f3,
                        const float* __restrict__ f4,
                        float* __restrict__ out, int N) {
    int p = (blockIdx.x * blockDim.x + threadIdx.x) >> 5;  // warp = point
    int lane = threadIdx.x & 31;
    if (p >= N) return;

    float X = __ldg(coord + 3 * p + 0);
    float Y = __ldg(coord + 3 * p + 1);
    float Z = __ldg(coord + 3 * p + 2);

    float h = 250.0f * (-Y) / (-Z) + 112.0f;
    float w = 250.0f * X / (-Z) + 112.0f;
    // clip to [0,223]; comparison form preserves jnp.clip NaN propagation
    h = (h < 0.0f) ? 0.0f : ((h > 223.0f) ? 223.0f : h);
    w = (w < 0.0f) ? 0.0f : ((w > 223.0f) ? 223.0f : w);

    float* __restrict__ orow = out + (size_t)p * OUT_COLS;
    if (lane == 0) orow[0] = X;
    if (lane == 1) orow[1] = Y;
    if (lane == 2) orow[2] = Z;

    // Fast path: h==0 or w==0 => integral grid coord at every level =>
    // all four bilinear weights exactly 0 => 960-channel block is 0.
    if (h == 0.0f || w == 0.0f) {
        float* z = orow + 3;
        int head = (int)(((16u - ((uint32_t)(uintptr_t)z & 15u)) & 15u) >> 2);
        if (lane < head) z[lane] = 0.0f;
        int nvec = (960 - head) >> 2;
        float4* v = (float4*)(z + head);
        float4 z4 = make_float4(0.f, 0.f, 0.f, 0.f);
#pragma unroll
        for (int i = 0; i < 8; ++i) {
            int idx = lane + 32 * i;
            if (idx < nvec) v[idx] = z4;
        }
        int done = head + 4 * nvec;
        if (lane < 960 - done) z[done + lane] = 0.0f;
        return;
    }

    // scales: 224/56=4, 224/28=8, 224/14=16, 224/7=32 (exact pow2 -> mul ok)
    bilerp_scalar<64, 56>(f1, h * 0.25f,    w * 0.25f,    orow + 3,   lane);
    bilerp_scalar<128, 28>(f2, h * 0.125f,  w * 0.125f,   orow + 67,  lane);
    bilerp_scalar<256, 14>(f3, h * 0.0625f, w * 0.0625f,  orow + 195, lane);
    bilerp_scalar<512, 7>(f4, h * 0.03125f, w * 0.03125f, orow + 451, lane);
}

extern "C" void kernel_launch(void* const* d_in, const int* in_sizes, int n_in,
                              void* d_out, int out_size) {
    const float* coord = (const float*)d_in[0];
    const float* f1 = (const float*)d_in[1];
    const float* f2 = (const float*)d_in[2];
    const float* f3 = (const float*)d_in[3];
    const float* f4 = (const float*)d_in[4];
    float* out = (float*)d_out;

    int N = in_sizes[0] / 3;

    int blocks = (N + 7) / 8;  // 8 warps/block, 1 point/warp
    graph_projection_kernel<<<blocks, 256>>>(coord, f1, f2, f3, f4, out, N);
}